// round 2
// baseline (speedup 1.0000x reference)
#include <cuda_runtime.h>
#include <math.h>

// Problem shape (fixed by setup_inputs): q [16,64,64,64] f32, keys [4096,64], values [4096,64]
#define MEM   4096
#define DIM   64
#define NQ    65536       // 16 * 64 * 64 queries
#define HW    4096        // H*W (spatial stride between channels)
#define CHS   262144      // per-batch stride = C*HW
#define TILE  128         // keys per smem tile (32 KB)
#define NTILES (MEM / TILE)

// Normalized keys (prolog kernel output). Static device scratch (no allocs).
__device__ float g_kn[MEM * DIM];

// ---------------- f32x2 packed-math helpers (sm_100+ FFMA2 path) ----------------
__device__ __forceinline__ unsigned long long pack2(float x, float y) {
    unsigned long long r;
    asm("mov.b64 %0, {%1, %2};" : "=l"(r) : "f"(x), "f"(y));
    return r;
}
__device__ __forceinline__ void fma2(unsigned long long& acc,
                                     unsigned long long a,
                                     unsigned long long b) {
    asm("fma.rn.f32x2 %0, %1, %2, %0;" : "+l"(acc) : "l"(a), "l"(b));
}
__device__ __forceinline__ float hsum2x2(unsigned long long a, unsigned long long b) {
    unsigned long long s;
    asm("add.rn.f32x2 %0, %1, %2;" : "=l"(s) : "l"(a), "l"(b));
    float lo = __int_as_float((int)(s & 0xffffffffull));
    float hi = __int_as_float((int)(s >> 32));
    return lo + hi;
}

// Sorted-descending top-8 insert (predicated bubble-up; caller guards s > v[7]).
// Strict '>' everywhere => stable w.r.t. key index, matching jax.lax.top_k ties.
__device__ __forceinline__ void insert8(float s, int k, float (&v)[8], int (&id)[8]) {
    v[7] = s; id[7] = k;
#pragma unroll
    for (int j = 7; j > 0; --j) {
        bool sw = v[j] > v[j - 1];
        float tv = v[j - 1]; int ti = id[j - 1];
        v[j - 1] = sw ? v[j] : v[j - 1];
        id[j - 1] = sw ? id[j] : id[j - 1];
        v[j] = sw ? tv : v[j];
        id[j] = sw ? ti : id[j];
    }
}

// ---------------- prolog: L2-normalize keys ----------------
__global__ void kvm_normalize_keys(const float* __restrict__ keys) {
    int k = blockIdx.x * blockDim.x + threadIdx.x;
    if (k >= MEM) return;
    const float4* kr = (const float4*)(keys + (size_t)k * DIM);
    float4 v[16];
    float ss = 0.f;
#pragma unroll
    for (int i = 0; i < 16; ++i) {
        v[i] = kr[i];
        ss += v[i].x * v[i].x + v[i].y * v[i].y + v[i].z * v[i].z + v[i].w * v[i].w;
    }
    float n = fmaxf(sqrtf(ss), 1e-12f);
    float4* o = (float4*)(g_kn + (size_t)k * DIM);
#pragma unroll
    for (int i = 0; i < 16; ++i) {
        float4 t;
        t.x = v[i].x / n; t.y = v[i].y / n; t.z = v[i].z / n; t.w = v[i].w / n;
        o[i] = t;
    }
}

// Load + normalize one query into 32 packed f32x2 registers.
__device__ __forceinline__ void load_query(const float* __restrict__ qp,
                                           unsigned long long (&qr)[32]) {
    float ss = 0.f;
#pragma unroll
    for (int c = 0; c < 64; ++c) {
        float x = qp[c * HW];
        ss += x * x;
    }
    float n = fmaxf(sqrtf(ss), 1e-12f);
#pragma unroll
    for (int p = 0; p < 32; ++p) {
        float x0 = qp[(2 * p) * HW] / n;
        float x1 = qp[(2 * p + 1) * HW] / n;
        qr[p] = pack2(x0, x1);
    }
}

// Softmax over sorted top-8 + weighted gather of value rows, strided store.
__device__ __forceinline__ void epilogue(const float* __restrict__ values,
                                         const float (&v)[8], const int (&id)[8],
                                         float* __restrict__ outp) {
    float w[8];
    float m = v[0];  // max (sorted descending)
    float sum = 0.f;
#pragma unroll
    for (int j = 0; j < 8; ++j) { w[j] = expf(v[j] - m); sum += w[j]; }
    float4 acc[16];
#pragma unroll
    for (int i = 0; i < 16; ++i) acc[i] = make_float4(0.f, 0.f, 0.f, 0.f);
#pragma unroll
    for (int j = 0; j < 8; ++j) {
        float wj = w[j] / sum;
        const float4* vr = (const float4*)(values + (size_t)id[j] * DIM);
#pragma unroll
        for (int i = 0; i < 16; ++i) {
            float4 x = vr[i];
            acc[i].x += wj * x.x; acc[i].y += wj * x.y;
            acc[i].z += wj * x.z; acc[i].w += wj * x.w;
        }
    }
    const float* af = (const float*)acc;
#pragma unroll
    for (int c = 0; c < 64; ++c) outp[c * HW] = af[c];
}

// ---------------- main kernel: 256 threads, 2 queries/thread, 512 q/block ----------------
__global__ void __launch_bounds__(256, 1)
kvm_main(const float* __restrict__ q,
         const float* __restrict__ values,
         float* __restrict__ out) {
    // 128 keys * 64 floats = 32 KB = 128 * 16 ulonglong2 (BUGFIX: was TILE*(DIM/8))
    __shared__ ulonglong2 skeys[TILE * 16];

    const int tid = threadIdx.x;
    const int g0 = blockIdx.x * 512 + tid;   // first query
    const int g1 = g0 + 256;                 // second query

    const int b0 = g0 >> 12, n0 = g0 & (HW - 1);
    const int b1 = g1 >> 12, n1 = g1 & (HW - 1);

    unsigned long long qa[32], qb[32];
    load_query(q + (size_t)b0 * CHS + n0, qa);
    load_query(q + (size_t)b1 * CHS + n1, qb);

    float va[8], vb[8];
    int ia[8], ib[8];
#pragma unroll
    for (int j = 0; j < 8; ++j) { va[j] = -1e30f; vb[j] = -1e30f; ia[j] = 0; ib[j] = 0; }

    for (int t = 0; t < NTILES; ++t) {
        __syncthreads();
        {
            const float4* src = (const float4*)(g_kn + (size_t)t * TILE * DIM);
            float4* dst = (float4*)skeys;
#pragma unroll
            for (int i = 0; i < 8; ++i) dst[tid + i * 256] = src[tid + i * 256];
        }
        __syncthreads();

        const int kbase = t * TILE;
        for (int kk = 0; kk < TILE; ++kk) {
            const ulonglong2* kp = skeys + kk * 16;
            unsigned long long a0 = 0ull, a1 = 0ull, b0a = 0ull, b1a = 0ull;
#pragma unroll
            for (int j = 0; j < 16; ++j) {
                ulonglong2 kv = kp[j];
                fma2(a0, qa[2 * j], kv.x);
                fma2(a1, qa[2 * j + 1], kv.y);
                fma2(b0a, qb[2 * j], kv.x);
                fma2(b1a, qb[2 * j + 1], kv.y);
            }
            float sa = hsum2x2(a0, a1);
            float sb = hsum2x2(b0a, b1a);
            int kid = kbase + kk;
            if (sa > va[7]) insert8(sa, kid, va, ia);
            if (sb > vb[7]) insert8(sb, kid, vb, ib);
        }
    }

    epilogue(values, va, ia, out + (size_t)b0 * CHS + n0);
    epilogue(values, vb, ib, out + (size_t)b1 * CHS + n1);
}

extern "C" void kernel_launch(void* const* d_in, const int* in_sizes, int n_in,
                              void* d_out, int out_size) {
    const float* q      = (const float*)d_in[0];
    const float* keys   = (const float*)d_in[1];
    const float* values = (const float*)d_in[2];
    float* out = (float*)d_out;

    kvm_normalize_keys<<<(MEM + 255) / 256, 256>>>(keys);
    kvm_main<<<NQ / 512, 256>>>(q, values, out);
}

// round 3
// speedup vs baseline: 1.0565x; 1.0565x over previous
#include <cuda_runtime.h>
#include <math.h>

// Problem shape (fixed by setup_inputs): q [16,64,64,64] f32, keys [4096,64], values [4096,64]
#define MEM   4096
#define DIM   64
#define NQ    65536       // 16 * 64 * 64 queries
#define HW    4096        // H*W (spatial stride between channels)
#define CHS   262144      // per-batch stride = C*HW
#define TILE  128         // keys per smem tile (32 KB)
#define NTILES (MEM / TILE)

// Normalized keys (prolog kernel output). Static device scratch (no allocs).
__device__ float g_kn[MEM * DIM];

// ---------------- f32x2 packed-math helpers (sm_100+ FFMA2 path) ----------------
__device__ __forceinline__ unsigned long long pack2(float x, float y) {
    unsigned long long r;
    asm("mov.b64 %0, {%1, %2};" : "=l"(r) : "f"(x), "f"(y));
    return r;
}
__device__ __forceinline__ void fma2(unsigned long long& acc,
                                     unsigned long long a,
                                     unsigned long long b) {
    asm("fma.rn.f32x2 %0, %1, %2, %0;" : "+l"(acc) : "l"(a), "l"(b));
}
__device__ __forceinline__ float hsum2x2(unsigned long long a, unsigned long long b) {
    unsigned long long s;
    asm("add.rn.f32x2 %0, %1, %2;" : "=l"(s) : "l"(a), "l"(b));
    float lo = __int_as_float((int)(s & 0xffffffffull));
    float hi = __int_as_float((int)(s >> 32));
    return lo + hi;
}

// Sorted-descending top-8 insert (predicated bubble-up; caller guards s > v[7]).
// Strict '>' everywhere => stable w.r.t. key index, matching jax.lax.top_k ties.
__device__ __forceinline__ void insert8(float s, int k, float (&v)[8], int (&id)[8]) {
    v[7] = s; id[7] = k;
#pragma unroll
    for (int j = 7; j > 0; --j) {
        bool sw = v[j] > v[j - 1];
        float tv = v[j - 1]; int ti = id[j - 1];
        v[j - 1] = sw ? v[j] : v[j - 1];
        id[j - 1] = sw ? id[j] : id[j - 1];
        v[j] = sw ? tv : v[j];
        id[j] = sw ? ti : id[j];
    }
}

// ---------------- prolog: L2-normalize keys ----------------
__global__ void kvm_normalize_keys(const float* __restrict__ keys) {
    int k = blockIdx.x * blockDim.x + threadIdx.x;
    if (k >= MEM) return;
    const float4* kr = (const float4*)(keys + (size_t)k * DIM);
    float4 v[16];
    float ss = 0.f;
#pragma unroll
    for (int i = 0; i < 16; ++i) {
        v[i] = kr[i];
        ss += v[i].x * v[i].x + v[i].y * v[i].y + v[i].z * v[i].z + v[i].w * v[i].w;
    }
    float n = fmaxf(sqrtf(ss), 1e-12f);
    float4* o = (float4*)(g_kn + (size_t)k * DIM);
#pragma unroll
    for (int i = 0; i < 16; ++i) {
        float4 t;
        t.x = v[i].x / n; t.y = v[i].y / n; t.z = v[i].z / n; t.w = v[i].w / n;
        o[i] = t;
    }
}

// Load + normalize one query into 32 packed f32x2 registers.
__device__ __forceinline__ void load_query(const float* __restrict__ qp,
                                           unsigned long long (&qr)[32]) {
    float ss = 0.f;
#pragma unroll
    for (int c = 0; c < 64; ++c) {
        float x = qp[c * HW];
        ss += x * x;
    }
    float n = fmaxf(sqrtf(ss), 1e-12f);
#pragma unroll
    for (int p = 0; p < 32; ++p) {
        float x0 = qp[(2 * p) * HW] / n;
        float x1 = qp[(2 * p + 1) * HW] / n;
        qr[p] = pack2(x0, x1);
    }
}

// Softmax over sorted top-8 + weighted gather of value rows, strided store.
__device__ __forceinline__ void epilogue(const float* __restrict__ values,
                                         const float (&v)[8], const int (&id)[8],
                                         float* __restrict__ outp) {
    float w[8];
    float m = v[0];  // max (sorted descending)
    float sum = 0.f;
#pragma unroll
    for (int j = 0; j < 8; ++j) { w[j] = expf(v[j] - m); sum += w[j]; }
    float4 acc[16];
#pragma unroll
    for (int i = 0; i < 16; ++i) acc[i] = make_float4(0.f, 0.f, 0.f, 0.f);
#pragma unroll
    for (int j = 0; j < 8; ++j) {
        float wj = w[j] / sum;
        const float4* vr = (const float4*)(values + (size_t)id[j] * DIM);
#pragma unroll
        for (int i = 0; i < 16; ++i) {
            float4 x = vr[i];
            acc[i].x += wj * x.x; acc[i].y += wj * x.y;
            acc[i].z += wj * x.z; acc[i].w += wj * x.w;
        }
    }
    const float* af = (const float*)acc;
#pragma unroll
    for (int c = 0; c < 64; ++c) outp[c * HW] = af[c];
}

// ---------------- main kernel: 256 threads, 2 queries/thread, 512 q/block ----------------
__global__ void __launch_bounds__(256, 1)
kvm_main(const float* __restrict__ q,
         const float* __restrict__ values,
         float* __restrict__ out) {
    // 128 keys * 64 floats = 32 KB = 128 * 16 ulonglong2 (BUGFIX: was TILE*(DIM/8))
    __shared__ ulonglong2 skeys[TILE * 16];

    const int tid = threadIdx.x;
    const int g0 = blockIdx.x * 512 + tid;   // first query
    const int g1 = g0 + 256;                 // second query

    const int b0 = g0 >> 12, n0 = g0 & (HW - 1);
    const int b1 = g1 >> 12, n1 = g1 & (HW - 1);

    unsigned long long qa[32], qb[32];
    load_query(q + (size_t)b0 * CHS + n0, qa);
    load_query(q + (size_t)b1 * CHS + n1, qb);

    float va[8], vb[8];
    int ia[8], ib[8];
#pragma unroll
    for (int j = 0; j < 8; ++j) { va[j] = -1e30f; vb[j] = -1e30f; ia[j] = 0; ib[j] = 0; }

    for (int t = 0; t < NTILES; ++t) {
        __syncthreads();
        {
            const float4* src = (const float4*)(g_kn + (size_t)t * TILE * DIM);
            float4* dst = (float4*)skeys;
#pragma unroll
            for (int i = 0; i < 8; ++i) dst[tid + i * 256] = src[tid + i * 256];
        }
        __syncthreads();

        const int kbase = t * TILE;
        for (int kk = 0; kk < TILE; ++kk) {
            const ulonglong2* kp = skeys + kk * 16;
            unsigned long long a0 = 0ull, a1 = 0ull, b0a = 0ull, b1a = 0ull;
#pragma unroll
            for (int j = 0; j < 16; ++j) {
                ulonglong2 kv = kp[j];
                fma2(a0, qa[2 * j], kv.x);
                fma2(a1, qa[2 * j + 1], kv.y);
                fma2(b0a, qb[2 * j], kv.x);
                fma2(b1a, qb[2 * j + 1], kv.y);
            }
            float sa = hsum2x2(a0, a1);
            float sb = hsum2x2(b0a, b1a);
            int kid = kbase + kk;
            if (sa > va[7]) insert8(sa, kid, va, ia);
            if (sb > vb[7]) insert8(sb, kid, vb, ib);
        }
    }

    epilogue(values, va, ia, out + (size_t)b0 * CHS + n0);
    epilogue(values, vb, ib, out + (size_t)b1 * CHS + n1);
}

extern "C" void kernel_launch(void* const* d_in, const int* in_sizes, int n_in,
                              void* d_out, int out_size) {
    const float* q      = (const float*)d_in[0];
    const float* keys   = (const float*)d_in[1];
    const float* values = (const float*)d_in[2];
    float* out = (float*)d_out;

    kvm_normalize_keys<<<(MEM + 255) / 256, 256>>>(keys);
    kvm_main<<<NQ / 512, 256>>>(q, values, out);
}